// round 2
// baseline (speedup 1.0000x reference)
#include <cuda_runtime.h>
#include <math.h>

// ---------------- problem constants ----------------
namespace {
constexpr int kB  = 4;
constexpr int kN  = 1024;
constexpr int kD  = 768;
constexpr int kH  = 12;
constexpr int kHD = 64;
constexpr int kGP = 49;
constexpr int kMLP = 3072;
constexpr int kT  = kB * kN;     // 4096 tokens
constexpr int kBH = kB * kH;     // 48 batched heads
constexpr int kQD = 3 * kD;      // 2304
}

// ---------------- scratch (device globals: no allocation allowed) ----------------
__device__ float g_xn [kT * kD];
__device__ float g_qkv[kT * kQD];
__device__ float g_S  [(size_t)kBH * kN * kN];   // scores, later the mixed attn A
__device__ float g_G  [(size_t)kBH * kN * kN];   // gw @ gw^T
__device__ float g_gw [kBH * kN * 64];           // softmaxed group weights, padded 49->64
__device__ float g_inv[kBH * kN];                // 1/(colsum+eps)
__device__ float g_ctx[kT * kD];                 // merged-head attention output
__device__ float g_y  [kT * kD];                 // after proj residual
__device__ float g_yn [kT * kD];
__device__ float g_hdn[kT * kMLP];

__device__ __forceinline__ float gelu_exact(float x) {
    return 0.5f * x * (1.0f + erff(x * 0.70710678118654752440f));
}

// ---------------- LayerNorm: one block (256 thr) per row of 768 ----------------
__global__ __launch_bounds__(256) void ln_kernel(const float* __restrict__ x,
                                                 const float* __restrict__ w,
                                                 const float* __restrict__ b,
                                                 float* __restrict__ out) {
    __shared__ float sh1[8], sh2[8];
    int row = blockIdx.x;
    int t = threadIdx.x;
    const float* xr = x + (size_t)row * kD;
    float v[3];
    float s = 0.f, s2 = 0.f;
#pragma unroll
    for (int i = 0; i < 3; i++) {
        v[i] = xr[t + i * 256];
        s  += v[i];
        s2 += v[i] * v[i];
    }
#pragma unroll
    for (int o = 16; o; o >>= 1) {
        s  += __shfl_xor_sync(0xffffffffu, s, o);
        s2 += __shfl_xor_sync(0xffffffffu, s2, o);
    }
    if ((t & 31) == 0) { sh1[t >> 5] = s; sh2[t >> 5] = s2; }
    __syncthreads();
    s = sh1[t & 7]; s2 = sh2[t & 7];
#pragma unroll
    for (int o = 4; o; o >>= 1) {
        s  += __shfl_xor_sync(0xffffffffu, s, o);
        s2 += __shfl_xor_sync(0xffffffffu, s2, o);
    }
    float mu   = s * (1.0f / kD);
    float var  = fmaxf(s2 * (1.0f / kD) - mu * mu, 0.f);
    float rstd = rsqrtf(var + 1e-5f);
    float* orow = out + (size_t)row * kD;
#pragma unroll
    for (int i = 0; i < 3; i++) {
        int c = t + i * 256;
        orow[c] = (v[i] - mu) * rstd * w[c] + b[c];
    }
}

// ---------------- dense SGEMM: C[M,Nc] = A[M,K] @ B[K,Nc] + bias (+gelu)(+res) --
// 64x64 tile, 256 threads, 4x4 per thread, K-chunk 16.
__global__ __launch_bounds__(256) void sgemm_kernel(
        const float* __restrict__ A, const float* __restrict__ Bm,
        const float* __restrict__ bias, const float* __restrict__ res,
        float* __restrict__ C, int M, int Nc, int K, int act) {
    __shared__ __align__(16) float As[16][72];
    __shared__ __align__(16) float Bs[16][72];
    int tid = threadIdx.x;
    int tx = tid & 15, ty = tid >> 4;
    int row0 = blockIdx.y * 64;
    int col0 = blockIdx.x * 64;
    int ar = tid >> 2, ac = (tid & 3) * 4;
    int bk = tid >> 4, bc = (tid & 15) * 4;
    const float* Aptr = A + (size_t)(row0 + ar) * K + ac;
    const float* Bptr = Bm + (size_t)bk * Nc + col0 + bc;
    float acc[4][4] = {};
    for (int k0 = 0; k0 < K; k0 += 16) {
        float4 av = *(const float4*)(Aptr + k0);
        float4 bv = *(const float4*)(Bptr + (size_t)k0 * Nc);
        As[ac + 0][ar] = av.x; As[ac + 1][ar] = av.y;
        As[ac + 2][ar] = av.z; As[ac + 3][ar] = av.w;
        *(float4*)&Bs[bk][bc] = bv;
        __syncthreads();
#pragma unroll
        for (int kk = 0; kk < 16; kk++) {
            float4 a = *(const float4*)&As[kk][ty * 4];
            float4 b = *(const float4*)&Bs[kk][tx * 4];
            acc[0][0] += a.x * b.x; acc[0][1] += a.x * b.y; acc[0][2] += a.x * b.z; acc[0][3] += a.x * b.w;
            acc[1][0] += a.y * b.x; acc[1][1] += a.y * b.y; acc[1][2] += a.y * b.z; acc[1][3] += a.y * b.w;
            acc[2][0] += a.z * b.x; acc[2][1] += a.z * b.y; acc[2][2] += a.z * b.z; acc[2][3] += a.z * b.w;
            acc[3][0] += a.w * b.x; acc[3][1] += a.w * b.y; acc[3][2] += a.w * b.z; acc[3][3] += a.w * b.w;
        }
        __syncthreads();
    }
    float4 bia = *(const float4*)&bias[col0 + tx * 4];
#pragma unroll
    for (int i = 0; i < 4; i++) {
        int r = row0 + ty * 4 + i;
        float4 o;
        o.x = acc[i][0] + bia.x; o.y = acc[i][1] + bia.y;
        o.z = acc[i][2] + bia.z; o.w = acc[i][3] + bia.w;
        if (act) {
            o.x = gelu_exact(o.x); o.y = gelu_exact(o.y);
            o.z = gelu_exact(o.z); o.w = gelu_exact(o.w);
        }
        if (res) {
            float4 rv = *(const float4*)&res[(size_t)r * Nc + col0 + tx * 4];
            o.x += rv.x; o.y += rv.y; o.z += rv.z; o.w += rv.w;
        }
        *(float4*)&C[(size_t)r * Nc + col0 + tx * 4] = o;
    }
}

// ---------------- scores S = scale * Q @ K^T, batched over BH ----------------
__global__ __launch_bounds__(256) void score_kernel(const float* __restrict__ qkv,
                                                    float* __restrict__ S) {
    int bh = blockIdx.z;
    int b = bh / kH, h = bh % kH;
    const float* qbase = qkv + (size_t)b * kN * kQD + h * kHD;
    const float* kbase = qbase + kD;
    int n0 = blockIdx.y * 64, m0 = blockIdx.x * 64;
    __shared__ __align__(16) float Qs[16][72];
    __shared__ __align__(16) float Ks[16][72];
    int tid = threadIdx.x;
    int tx = tid & 15, ty = tid >> 4;
    int ar = tid >> 2, ac = (tid & 3) * 4;
    float acc[4][4] = {};
    for (int k0 = 0; k0 < kHD; k0 += 16) {
        float4 qv = *(const float4*)(qbase + (size_t)(n0 + ar) * kQD + k0 + ac);
        float4 kv = *(const float4*)(kbase + (size_t)(m0 + ar) * kQD + k0 + ac);
        Qs[ac + 0][ar] = qv.x; Qs[ac + 1][ar] = qv.y;
        Qs[ac + 2][ar] = qv.z; Qs[ac + 3][ar] = qv.w;
        Ks[ac + 0][ar] = kv.x; Ks[ac + 1][ar] = kv.y;
        Ks[ac + 2][ar] = kv.z; Ks[ac + 3][ar] = kv.w;
        __syncthreads();
#pragma unroll
        for (int kk = 0; kk < 16; kk++) {
            float4 a = *(const float4*)&Qs[kk][ty * 4];
            float4 b2 = *(const float4*)&Ks[kk][tx * 4];
            acc[0][0] += a.x * b2.x; acc[0][1] += a.x * b2.y; acc[0][2] += a.x * b2.z; acc[0][3] += a.x * b2.w;
            acc[1][0] += a.y * b2.x; acc[1][1] += a.y * b2.y; acc[1][2] += a.y * b2.z; acc[1][3] += a.y * b2.w;
            acc[2][0] += a.z * b2.x; acc[2][1] += a.z * b2.y; acc[2][2] += a.z * b2.z; acc[2][3] += a.z * b2.w;
            acc[3][0] += a.w * b2.x; acc[3][1] += a.w * b2.y; acc[3][2] += a.w * b2.z; acc[3][3] += a.w * b2.w;
        }
        __syncthreads();
    }
    float* Sb = S + (size_t)bh * kN * kN;
#pragma unroll
    for (int i = 0; i < 4; i++) {
        size_t base = (size_t)(n0 + ty * 4 + i) * kN + m0 + tx * 4;
        float4 o = make_float4(acc[i][0] * 0.125f, acc[i][1] * 0.125f,
                               acc[i][2] * 0.125f, acc[i][3] * 0.125f);
        *(float4*)&Sb[base] = o;
    }
}

// ---------------- group weights: gw = softmax(gelu(V @ gp^T)) padded to 64 ----
__global__ __launch_bounds__(64) void gw_kernel(const float* __restrict__ qkv,
                                                const float* __restrict__ gp_w,
                                                float* __restrict__ gw) {
    __shared__ float vsm[64];
    __shared__ float red[64];
    int n = blockIdx.x, bh = blockIdx.y;
    int b = bh / kH, h = bh % kH;
    int t = threadIdx.x;
    vsm[t] = qkv[(size_t)(b * kN + n) * kQD + 2 * kD + h * kHD + t];
    __syncthreads();
    float acc = 0.f;
    if (t < kGP) {
        const float* gprow = gp_w + h * kGP * kHD + t * kHD;
#pragma unroll
        for (int d = 0; d < kHD; d++) acc += vsm[d] * gprow[d];
        acc = gelu_exact(acc);
    }
    red[t] = (t < kGP) ? acc : -1e30f;
    __syncthreads();
    for (int s = 32; s > 0; s >>= 1) {
        if (t < s) red[t] = fmaxf(red[t], red[t + s]);
        __syncthreads();
    }
    float mx = red[0];
    __syncthreads();
    float e = (t < kGP) ? expf(acc - mx) : 0.f;
    red[t] = e;
    __syncthreads();
    for (int s = 32; s > 0; s >>= 1) {
        if (t < s) red[t] += red[t + s];
        __syncthreads();
    }
    float inv = 1.f / red[0];
    gw[(size_t)(bh * kN + n) * 64 + t] = e * inv;
}

// ---------------- G = gw @ gw^T (K=64 padded, zeros harmless) ----------------
__global__ __launch_bounds__(256) void gmat_kernel(const float* __restrict__ gw,
                                                   float* __restrict__ G) {
    int bh = blockIdx.z;
    const float* gbase = gw + (size_t)bh * kN * 64;
    int n0 = blockIdx.y * 64, m0 = blockIdx.x * 64;
    __shared__ __align__(16) float Asm[16][72];
    __shared__ __align__(16) float Bsm[16][72];
    int tid = threadIdx.x;
    int tx = tid & 15, ty = tid >> 4;
    int ar = tid >> 2, ac = (tid & 3) * 4;
    float acc[4][4] = {};
    for (int k0 = 0; k0 < 64; k0 += 16) {
        float4 av = *(const float4*)(gbase + (size_t)(n0 + ar) * 64 + k0 + ac);
        float4 bv = *(const float4*)(gbase + (size_t)(m0 + ar) * 64 + k0 + ac);
        Asm[ac + 0][ar] = av.x; Asm[ac + 1][ar] = av.y;
        Asm[ac + 2][ar] = av.z; Asm[ac + 3][ar] = av.w;
        Bsm[ac + 0][ar] = bv.x; Bsm[ac + 1][ar] = bv.y;
        Bsm[ac + 2][ar] = bv.z; Bsm[ac + 3][ar] = bv.w;
        __syncthreads();
#pragma unroll
        for (int kk = 0; kk < 16; kk++) {
            float4 a = *(const float4*)&Asm[kk][ty * 4];
            float4 b2 = *(const float4*)&Bsm[kk][tx * 4];
            acc[0][0] += a.x * b2.x; acc[0][1] += a.x * b2.y; acc[0][2] += a.x * b2.z; acc[0][3] += a.x * b2.w;
            acc[1][0] += a.y * b2.x; acc[1][1] += a.y * b2.y; acc[1][2] += a.y * b2.z; acc[1][3] += a.y * b2.w;
            acc[2][0] += a.z * b2.x; acc[2][1] += a.z * b2.y; acc[2][2] += a.z * b2.z; acc[2][3] += a.z * b2.w;
            acc[3][0] += a.w * b2.x; acc[3][1] += a.w * b2.y; acc[3][2] += a.w * b2.z; acc[3][3] += a.w * b2.w;
        }
        __syncthreads();
    }
    float* Gb = G + (size_t)bh * kN * kN;
#pragma unroll
    for (int i = 0; i < 4; i++) {
        size_t base = (size_t)(n0 + ty * 4 + i) * kN + m0 + tx * 4;
        *(float4*)&Gb[base] = make_float4(acc[i][0], acc[i][1], acc[i][2], acc[i][3]);
    }
}

// ------- per-row: P = softmax(S*G); A = (1-a)P + a*G  (A overwrites S) -------
__global__ __launch_bounds__(256) void rowmix_kernel(const float* __restrict__ alpha,
                                                     float* __restrict__ S,
                                                     const float* __restrict__ G) {
    __shared__ float sh1[8];
    int gr = blockIdx.x;                 // bh*N + n
    int h = (gr >> 10) % kH;
    size_t off = (size_t)gr * kN;
    int t = threadIdx.x;
    float a = 1.f / (1.f + expf(-alpha[h]));
    float sv[4], gv[4], tv[4];
    float mx = -1e30f;
#pragma unroll
    for (int i = 0; i < 4; i++) {
        int m = t + i * 256;
        sv[i] = S[off + m];
        gv[i] = G[off + m];
        tv[i] = sv[i] * gv[i];
        mx = fmaxf(mx, tv[i]);
    }
    for (int o = 16; o; o >>= 1) mx = fmaxf(mx, __shfl_xor_sync(0xffffffffu, mx, o));
    if ((t & 31) == 0) sh1[t >> 5] = mx;
    __syncthreads();
    mx = sh1[t & 7];
    for (int o = 4; o; o >>= 1) mx = fmaxf(mx, __shfl_xor_sync(0xffffffffu, mx, o));
    __syncthreads();
    float e[4], sum = 0.f;
#pragma unroll
    for (int i = 0; i < 4; i++) { e[i] = expf(tv[i] - mx); sum += e[i]; }
    for (int o = 16; o; o >>= 1) sum += __shfl_xor_sync(0xffffffffu, sum, o);
    if ((t & 31) == 0) sh1[t >> 5] = sum;
    __syncthreads();
    sum = sh1[t & 7];
    for (int o = 4; o; o >>= 1) sum += __shfl_xor_sync(0xffffffffu, sum, o);
    float isum = 1.f / sum;
#pragma unroll
    for (int i = 0; i < 4; i++) {
        int m = t + i * 256;
        S[off + m] = (1.f - a) * e[i] * isum + a * gv[i];
    }
}

// ------- column sums over n (axis=2), stores 1/(sum+1e-8) -------
__global__ __launch_bounds__(256) void colsum_kernel(const float* __restrict__ Sa,
                                                     float* __restrict__ inv) {
    int idx = blockIdx.x * 256 + threadIdx.x;   // bh*N + m
    int bh = idx >> 10, m = idx & 1023;
    const float* p = Sa + (size_t)bh * kN * kN + m;
    float s = 0.f;
#pragma unroll 4
    for (int n = 0; n < kN; n++) s += p[(size_t)n * kN];
    inv[idx] = 1.f / (s + 1e-8f);
}

// ------- out = (A * inv[m]) @ V, heads merged directly into ctx[b,n,dim] ------
__global__ __launch_bounds__(256) void av_kernel(const float* __restrict__ Sa,
                                                 const float* __restrict__ inv,
                                                 const float* __restrict__ qkv,
                                                 float* __restrict__ ctx) {
    int bh = blockIdx.z;
    int b = bh / kH, h = bh % kH;
    int n0 = blockIdx.y * 64;
    const float* Abase = Sa + (size_t)bh * kN * kN;
    const float* vbase = qkv + (size_t)b * kN * kQD + 2 * kD + h * kHD;
    const float* invb = inv + bh * kN;
    __shared__ __align__(16) float As[16][72];
    __shared__ __align__(16) float Vs[16][72];
    int tid = threadIdx.x;
    int tx = tid & 15, ty = tid >> 4;
    int ar = tid >> 2, ac = (tid & 3) * 4;
    int bk = tid >> 4, bc = (tid & 15) * 4;
    float acc[4][4] = {};
    for (int k0 = 0; k0 < kN; k0 += 16) {
        float4 av = *(const float4*)(Abase + (size_t)(n0 + ar) * kN + k0 + ac);
        float iv = invb[k0 + bk];
        float4 vv = *(const float4*)(vbase + (size_t)(k0 + bk) * kQD + bc);
        As[ac + 0][ar] = av.x; As[ac + 1][ar] = av.y;
        As[ac + 2][ar] = av.z; As[ac + 3][ar] = av.w;
        *(float4*)&Vs[bk][bc] = make_float4(vv.x * iv, vv.y * iv, vv.z * iv, vv.w * iv);
        __syncthreads();
#pragma unroll
        for (int kk = 0; kk < 16; kk++) {
            float4 a = *(const float4*)&As[kk][ty * 4];
            float4 b2 = *(const float4*)&Vs[kk][tx * 4];
            acc[0][0] += a.x * b2.x; acc[0][1] += a.x * b2.y; acc[0][2] += a.x * b2.z; acc[0][3] += a.x * b2.w;
            acc[1][0] += a.y * b2.x; acc[1][1] += a.y * b2.y; acc[1][2] += a.y * b2.z; acc[1][3] += a.y * b2.w;
            acc[2][0] += a.z * b2.x; acc[2][1] += a.z * b2.y; acc[2][2] += a.z * b2.z; acc[2][3] += a.z * b2.w;
            acc[3][0] += a.w * b2.x; acc[3][1] += a.w * b2.y; acc[3][2] += a.w * b2.z; acc[3][3] += a.w * b2.w;
        }
        __syncthreads();
    }
#pragma unroll
    for (int i = 0; i < 4; i++) {
        int n = n0 + ty * 4 + i;
        size_t base = (size_t)(b * kN + n) * kD + h * kHD + tx * 4;
        *(float4*)&ctx[base] = make_float4(acc[i][0], acc[i][1], acc[i][2], acc[i][3]);
    }
}

// ---------------- launch ----------------
extern "C" void kernel_launch(void* const* d_in, const int* in_sizes, int n_in,
                              void* d_out, int out_size) {
    const float* x      = (const float*)d_in[0];
    const float* ln1_w  = (const float*)d_in[1];
    const float* ln1_b  = (const float*)d_in[2];
    const float* qkv_w  = (const float*)d_in[3];
    const float* qkv_b  = (const float*)d_in[4];
    const float* proj_w = (const float*)d_in[5];
    const float* proj_b = (const float*)d_in[6];
    const float* gp_w   = (const float*)d_in[7];
    const float* alpha  = (const float*)d_in[8];
    const float* ln2_w  = (const float*)d_in[9];
    const float* ln2_b  = (const float*)d_in[10];
    const float* ff1_w  = (const float*)d_in[11];
    const float* ff1_b  = (const float*)d_in[12];
    const float* ff2_w  = (const float*)d_in[13];
    const float* ff2_b  = (const float*)d_in[14];
    float* out = (float*)d_out;

    float *xn, *qkv, *S, *G, *gw, *inv, *ctx, *y, *yn, *hdn;
    cudaGetSymbolAddress((void**)&xn,  g_xn);
    cudaGetSymbolAddress((void**)&qkv, g_qkv);
    cudaGetSymbolAddress((void**)&S,   g_S);
    cudaGetSymbolAddress((void**)&G,   g_G);
    cudaGetSymbolAddress((void**)&gw,  g_gw);
    cudaGetSymbolAddress((void**)&inv, g_inv);
    cudaGetSymbolAddress((void**)&ctx, g_ctx);
    cudaGetSymbolAddress((void**)&y,   g_y);
    cudaGetSymbolAddress((void**)&yn,  g_yn);
    cudaGetSymbolAddress((void**)&hdn, g_hdn);

    // attention branch
    ln_kernel<<<kT, 256>>>(x, ln1_w, ln1_b, xn);
    sgemm_kernel<<<dim3(kQD / 64, kT / 64), 256>>>(xn, qkv_w, qkv_b, nullptr, qkv,
                                                   kT, kQD, kD, 0);
    score_kernel<<<dim3(16, 16, kBH), 256>>>(qkv, S);
    gw_kernel<<<dim3(kN, kBH), 64>>>(qkv, gp_w, gw);
    gmat_kernel<<<dim3(16, 16, kBH), 256>>>(gw, G);
    rowmix_kernel<<<kBH * kN, 256>>>(alpha, S, G);
    colsum_kernel<<<kBH * kN / 256, 256>>>(S, inv);
    av_kernel<<<dim3(1, 16, kBH), 256>>>(S, inv, qkv, ctx);
    sgemm_kernel<<<dim3(kD / 64, kT / 64), 256>>>(ctx, proj_w, proj_b, x, y,
                                                  kT, kD, kD, 0);
    // FFN branch
    ln_kernel<<<kT, 256>>>(y, ln2_w, ln2_b, yn);
    sgemm_kernel<<<dim3(kMLP / 64, kT / 64), 256>>>(yn, ff1_w, ff1_b, nullptr, hdn,
                                                    kT, kMLP, kD, 1);
    sgemm_kernel<<<dim3(kD / 64, kT / 64), 256>>>(hdn, ff2_w, ff2_b, y, out,
                                                  kT, kD, kMLP, 0);
}

// round 3
// speedup vs baseline: 1.0137x; 1.0137x over previous
#include <cuda_runtime.h>
#include <math.h>

// ---------------- problem constants ----------------
namespace {
constexpr int kB  = 4;
constexpr int kN  = 1024;
constexpr int kD  = 768;
constexpr int kH  = 12;
constexpr int kHD = 64;
constexpr int kGP = 49;
constexpr int kMLP = 3072;
constexpr int kT  = kB * kN;     // 4096 tokens
constexpr int kBH = kB * kH;     // 48 batched heads
constexpr int kQD = 3 * kD;      // 2304
}

// ---------------- scratch (device globals: no allocation allowed) ----------------
__device__ float g_xn [kT * kD];
__device__ float g_qkv[kT * kQD];
__device__ float g_S  [(size_t)kBH * kN * kN];   // scores, later the mixed attn A
__device__ float g_G  [(size_t)kBH * kN * kN];   // gw @ gw^T
__device__ float g_gw [kBH * kN * 64];           // softmaxed group weights, padded 49->64
__device__ float g_inv[kBH * kN];                // 1/(colsum+eps)
__device__ float g_ctx[kT * kD];                 // merged-head attention output
__device__ float g_y  [kT * kD];                 // after proj residual
__device__ float g_yn [kT * kD];
__device__ float g_hdn[kT * kMLP];

__device__ __forceinline__ float gelu_exact(float x) {
    return 0.5f * x * (1.0f + erff(x * 0.70710678118654752440f));
}

// ---------------- LayerNorm: one block (256 thr) per row of 768 ----------------
__global__ __launch_bounds__(256) void ln_kernel(const float* __restrict__ x,
                                                 const float* __restrict__ w,
                                                 const float* __restrict__ b,
                                                 float* __restrict__ out) {
    __shared__ float sh1[8], sh2[8];
    int row = blockIdx.x;
    int t = threadIdx.x;
    const float* xr = x + (size_t)row * kD;
    float v[3];
    float s = 0.f, s2 = 0.f;
#pragma unroll
    for (int i = 0; i < 3; i++) {
        v[i] = xr[t + i * 256];
        s  += v[i];
        s2 += v[i] * v[i];
    }
#pragma unroll
    for (int o = 16; o; o >>= 1) {
        s  += __shfl_xor_sync(0xffffffffu, s, o);
        s2 += __shfl_xor_sync(0xffffffffu, s2, o);
    }
    if ((t & 31) == 0) { sh1[t >> 5] = s; sh2[t >> 5] = s2; }
    __syncthreads();
    s = sh1[t & 7]; s2 = sh2[t & 7];
#pragma unroll
    for (int o = 4; o; o >>= 1) {
        s  += __shfl_xor_sync(0xffffffffu, s, o);
        s2 += __shfl_xor_sync(0xffffffffu, s2, o);
    }
    float mu   = s * (1.0f / kD);
    float var  = fmaxf(s2 * (1.0f / kD) - mu * mu, 0.f);
    float rstd = rsqrtf(var + 1e-5f);
    float* orow = out + (size_t)row * kD;
#pragma unroll
    for (int i = 0; i < 3; i++) {
        int c = t + i * 256;
        orow[c] = (v[i] - mu) * rstd * w[c] + b[c];
    }
}

// ------- dense SGEMM: C[M,Nc] = A[M,K] @ B[K,Nc] + bias (+gelu)(+res) --------
// 128x128 tile, 256 threads, 8x8 per thread, K-chunk 8.
__global__ __launch_bounds__(256) void sgemm128_kernel(
        const float* __restrict__ A, const float* __restrict__ Bm,
        const float* __restrict__ bias, const float* __restrict__ res,
        float* __restrict__ C, int M, int Nc, int K, int act) {
    __shared__ __align__(16) float As[8][132];
    __shared__ __align__(16) float Bs[8][128];
    int tid = threadIdx.x;
    int tx = tid & 15, ty = tid >> 4;       // 16 x 16 thread grid, 8x8 each
    int row0 = blockIdx.y * 128;
    int col0 = blockIdx.x * 128;
    // A loader: 128 rows x 8 cols, 2 threads per row (float4 each)
    int ar = tid >> 1, ac = (tid & 1) * 4;
    // B loader: 8 rows x 128 cols, 32 threads per row (float4 each)
    int bk = tid >> 5, bc = (tid & 31) * 4;
    const float* Aptr = A + (size_t)(row0 + ar) * K + ac;
    const float* Bptr = Bm + (size_t)bk * Nc + col0 + bc;
    float acc[8][8] = {};
    float a[8], b[8];
    for (int k0 = 0; k0 < K; k0 += 8) {
        float4 av = *(const float4*)(Aptr + k0);
        float4 bv = *(const float4*)(Bptr + (size_t)k0 * Nc);
        As[ac + 0][ar] = av.x; As[ac + 1][ar] = av.y;
        As[ac + 2][ar] = av.z; As[ac + 3][ar] = av.w;
        *(float4*)&Bs[bk][bc] = bv;
        __syncthreads();
#pragma unroll
        for (int kk = 0; kk < 8; kk++) {
            *(float4*)&a[0] = *(const float4*)&As[kk][ty * 8];
            *(float4*)&a[4] = *(const float4*)&As[kk][ty * 8 + 4];
            *(float4*)&b[0] = *(const float4*)&Bs[kk][tx * 8];
            *(float4*)&b[4] = *(const float4*)&Bs[kk][tx * 8 + 4];
#pragma unroll
            for (int i = 0; i < 8; i++)
#pragma unroll
                for (int j = 0; j < 8; j++)
                    acc[i][j] += a[i] * b[j];
        }
        __syncthreads();
    }
    float bia[8];
    *(float4*)&bia[0] = *(const float4*)&bias[col0 + tx * 8];
    *(float4*)&bia[4] = *(const float4*)&bias[col0 + tx * 8 + 4];
#pragma unroll
    for (int i = 0; i < 8; i++) {
        int r = row0 + ty * 8 + i;
        float o[8];
#pragma unroll
        for (int j = 0; j < 8; j++) {
            o[j] = acc[i][j] + bia[j];
            if (act) o[j] = gelu_exact(o[j]);
        }
        if (res) {
            float rv[8];
            *(float4*)&rv[0] = *(const float4*)&res[(size_t)r * Nc + col0 + tx * 8];
            *(float4*)&rv[4] = *(const float4*)&res[(size_t)r * Nc + col0 + tx * 8 + 4];
#pragma unroll
            for (int j = 0; j < 8; j++) o[j] += rv[j];
        }
        *(float4*)&C[(size_t)r * Nc + col0 + tx * 8]     = *(float4*)&o[0];
        *(float4*)&C[(size_t)r * Nc + col0 + tx * 8 + 4] = *(float4*)&o[4];
    }
}

// ---------------- scores S = scale * Q @ K^T, batched over BH ----------------
__global__ __launch_bounds__(256) void score_kernel(const float* __restrict__ qkv,
                                                    float* __restrict__ S) {
    int bh = blockIdx.z;
    int b = bh / kH, h = bh % kH;
    const float* qbase = qkv + (size_t)b * kN * kQD + h * kHD;
    const float* kbase = qbase + kD;
    int n0 = blockIdx.y * 64, m0 = blockIdx.x * 64;
    __shared__ __align__(16) float Qs[16][72];
    __shared__ __align__(16) float Ks[16][72];
    int tid = threadIdx.x;
    int tx = tid & 15, ty = tid >> 4;
    int ar = tid >> 2, ac = (tid & 3) * 4;
    float acc[4][4] = {};
    for (int k0 = 0; k0 < kHD; k0 += 16) {
        float4 qv = *(const float4*)(qbase + (size_t)(n0 + ar) * kQD + k0 + ac);
        float4 kv = *(const float4*)(kbase + (size_t)(m0 + ar) * kQD + k0 + ac);
        Qs[ac + 0][ar] = qv.x; Qs[ac + 1][ar] = qv.y;
        Qs[ac + 2][ar] = qv.z; Qs[ac + 3][ar] = qv.w;
        Ks[ac + 0][ar] = kv.x; Ks[ac + 1][ar] = kv.y;
        Ks[ac + 2][ar] = kv.z; Ks[ac + 3][ar] = kv.w;
        __syncthreads();
#pragma unroll
        for (int kk = 0; kk < 16; kk++) {
            float4 a = *(const float4*)&Qs[kk][ty * 4];
            float4 b2 = *(const float4*)&Ks[kk][tx * 4];
            acc[0][0] += a.x * b2.x; acc[0][1] += a.x * b2.y; acc[0][2] += a.x * b2.z; acc[0][3] += a.x * b2.w;
            acc[1][0] += a.y * b2.x; acc[1][1] += a.y * b2.y; acc[1][2] += a.y * b2.z; acc[1][3] += a.y * b2.w;
            acc[2][0] += a.z * b2.x; acc[2][1] += a.z * b2.y; acc[2][2] += a.z * b2.z; acc[2][3] += a.z * b2.w;
            acc[3][0] += a.w * b2.x; acc[3][1] += a.w * b2.y; acc[3][2] += a.w * b2.z; acc[3][3] += a.w * b2.w;
        }
        __syncthreads();
    }
    float* Sb = S + (size_t)bh * kN * kN;
#pragma unroll
    for (int i = 0; i < 4; i++) {
        size_t base = (size_t)(n0 + ty * 4 + i) * kN + m0 + tx * 4;
        float4 o = make_float4(acc[i][0] * 0.125f, acc[i][1] * 0.125f,
                               acc[i][2] * 0.125f, acc[i][3] * 0.125f);
        *(float4*)&Sb[base] = o;
    }
}

// ---- group weights: gw = softmax(gelu(V @ gp^T)) padded to 64 ----
// One block = (bh, 64-row tile). gp head slice + V tile staged in smem.
// 4 threads per row; each handles cols c0, c0+4, ... (13 each); shuffle softmax.
__global__ __launch_bounds__(256) void gw_kernel(const float* __restrict__ qkv,
                                                 const float* __restrict__ gp_w,
                                                 float* __restrict__ gw) {
    __shared__ __align__(16) float gps[kGP][68];
    __shared__ __align__(16) float Vs[64][68];
    int bh = blockIdx.y;
    int b = bh / kH, h = bh % kH;
    int n0 = blockIdx.x * 64;
    int tid = threadIdx.x;
    // load gp head slice [49][64]
    const float* gph = gp_w + (size_t)h * kGP * kHD;
    for (int i = tid; i < kGP * 16; i += 256) {    // 49*16 float4s
        int r = i >> 4, c4 = (i & 15) * 4;
        *(float4*)&gps[r][c4] = *(const float4*)(gph + r * kHD + c4);
    }
    // load V tile [64][64]
    const float* vb = qkv + (size_t)(b * kN + n0) * kQD + 2 * kD + h * kHD;
    for (int i = tid; i < 64 * 16; i += 256) {
        int r = i >> 4, c4 = (i & 15) * 4;
        *(float4*)&Vs[r][c4] = *(const float4*)(vb + (size_t)r * kQD + c4);
    }
    __syncthreads();
    int r = tid >> 2;          // row within tile, 0..63
    int c0 = tid & 3;          // col group
    // 13 columns per thread: c = c0 + 4*j  (covers 0..51; guard c<49)
    float val[13];
    float mx = -1e30f;
#pragma unroll
    for (int j = 0; j < 13; j++) {
        int c = c0 + 4 * j;
        float acc = 0.f;
        if (c < kGP) {
#pragma unroll
            for (int d = 0; d < kHD; d += 4) {
                float4 vv = *(const float4*)&Vs[r][d];
                float4 gg = *(const float4*)&gps[c][d];
                acc += vv.x * gg.x + vv.y * gg.y + vv.z * gg.z + vv.w * gg.w;
            }
            acc = gelu_exact(acc);
            mx = fmaxf(mx, acc);
        }
        val[j] = acc;
    }
    // group-of-4 reduce (same warp, adjacent lanes)
    mx = fmaxf(mx, __shfl_xor_sync(0xffffffffu, mx, 1));
    mx = fmaxf(mx, __shfl_xor_sync(0xffffffffu, mx, 2));
    float sum = 0.f;
#pragma unroll
    for (int j = 0; j < 13; j++) {
        int c = c0 + 4 * j;
        val[j] = (c < kGP) ? expf(val[j] - mx) : 0.f;
        sum += val[j];
    }
    sum += __shfl_xor_sync(0xffffffffu, sum, 1);
    sum += __shfl_xor_sync(0xffffffffu, sum, 2);
    float inv = 1.f / sum;
    float* grow = gw + (size_t)(bh * kN + n0 + r) * 64;
#pragma unroll
    for (int j = 0; j < 13; j++) {
        int c = c0 + 4 * j;
        if (c < 64) grow[c] = val[j] * inv;
    }
    // pad cols 52..63 handled above only for matching c0 lanes; cover the rest
    for (int c = 52 + c0; c < 64; c += 4) grow[c] = (c >= 52 && ((c - c0) % 4 == 0)) ? grow[c] : 0.f;
}

// ---------------- G = gw @ gw^T (K=64 padded, zeros harmless) ----------------
__global__ __launch_bounds__(256) void gmat_kernel(const float* __restrict__ gw,
                                                   float* __restrict__ G) {
    int bh = blockIdx.z;
    const float* gbase = gw + (size_t)bh * kN * 64;
    int n0 = blockIdx.y * 64, m0 = blockIdx.x * 64;
    __shared__ __align__(16) float Asm[16][72];
    __shared__ __align__(16) float Bsm[16][72];
    int tid = threadIdx.x;
    int tx = tid & 15, ty = tid >> 4;
    int ar = tid >> 2, ac = (tid & 3) * 4;
    float acc[4][4] = {};
    for (int k0 = 0; k0 < 64; k0 += 16) {
        float4 av = *(const float4*)(gbase + (size_t)(n0 + ar) * 64 + k0 + ac);
        float4 bv = *(const float4*)(gbase + (size_t)(m0 + ar) * 64 + k0 + ac);
        Asm[ac + 0][ar] = av.x; Asm[ac + 1][ar] = av.y;
        Asm[ac + 2][ar] = av.z; Asm[ac + 3][ar] = av.w;
        Bsm[ac + 0][ar] = bv.x; Bsm[ac + 1][ar] = bv.y;
        Bsm[ac + 2][ar] = bv.z; Bsm[ac + 3][ar] = bv.w;
        __syncthreads();
#pragma unroll
        for (int kk = 0; kk < 16; kk++) {
            float4 a = *(const float4*)&Asm[kk][ty * 4];
            float4 b2 = *(const float4*)&Bsm[kk][tx * 4];
            acc[0][0] += a.x * b2.x; acc[0][1] += a.x * b2.y; acc[0][2] += a.x * b2.z; acc[0][3] += a.x * b2.w;
            acc[1][0] += a.y * b2.x; acc[1][1] += a.y * b2.y; acc[1][2] += a.y * b2.z; acc[1][3] += a.y * b2.w;
            acc[2][0] += a.z * b2.x; acc[2][1] += a.z * b2.y; acc[2][2] += a.z * b2.z; acc[2][3] += a.z * b2.w;
            acc[3][0] += a.w * b2.x; acc[3][1] += a.w * b2.y; acc[3][2] += a.w * b2.z; acc[3][3] += a.w * b2.w;
        }
        __syncthreads();
    }
    float* Gb = G + (size_t)bh * kN * kN;
#pragma unroll
    for (int i = 0; i < 4; i++) {
        size_t base = (size_t)(n0 + ty * 4 + i) * kN + m0 + tx * 4;
        *(float4*)&Gb[base] = make_float4(acc[i][0], acc[i][1], acc[i][2], acc[i][3]);
    }
}

// ------- per-row: P = softmax(S*G); A = (1-a)P + a*G  (A overwrites S) -------
__global__ __launch_bounds__(256) void rowmix_kernel(const float* __restrict__ alpha,
                                                     float* __restrict__ S,
                                                     const float* __restrict__ G) {
    __shared__ float sh1[8];
    int gr = blockIdx.x;                 // bh*N + n
    int h = (gr >> 10) % kH;
    size_t off = (size_t)gr * kN;
    int t = threadIdx.x;
    float a = 1.f / (1.f + expf(-alpha[h]));
    float sv[4], gv[4], tv[4];
    float mx = -1e30f;
#pragma unroll
    for (int i = 0; i < 4; i++) {
        int m = t + i * 256;
        sv[i] = S[off + m];
        gv[i] = G[off + m];
        tv[i] = sv[i] * gv[i];
        mx = fmaxf(mx, tv[i]);
    }
    for (int o = 16; o; o >>= 1) mx = fmaxf(mx, __shfl_xor_sync(0xffffffffu, mx, o));
    if ((t & 31) == 0) sh1[t >> 5] = mx;
    __syncthreads();
    mx = sh1[t & 7];
    for (int o = 4; o; o >>= 1) mx = fmaxf(mx, __shfl_xor_sync(0xffffffffu, mx, o));
    __syncthreads();
    float e[4], sum = 0.f;
#pragma unroll
    for (int i = 0; i < 4; i++) { e[i] = expf(tv[i] - mx); sum += e[i]; }
    for (int o = 16; o; o >>= 1) sum += __shfl_xor_sync(0xffffffffu, sum, o);
    if ((t & 31) == 0) sh1[t >> 5] = sum;
    __syncthreads();
    sum = sh1[t & 7];
    for (int o = 4; o; o >>= 1) sum += __shfl_xor_sync(0xffffffffu, sum, o);
    float isum = 1.f / sum;
#pragma unroll
    for (int i = 0; i < 4; i++) {
        int m = t + i * 256;
        S[off + m] = (1.f - a) * e[i] * isum + a * gv[i];
    }
}

// ------- column sums over n (axis=2), stores 1/(sum+1e-8) -------
__global__ __launch_bounds__(256) void colsum_kernel(const float* __restrict__ Sa,
                                                     float* __restrict__ inv) {
    int idx = blockIdx.x * 256 + threadIdx.x;   // bh*N + m
    int bh = idx >> 10, m = idx & 1023;
    const float* p = Sa + (size_t)bh * kN * kN + m;
    float s = 0.f;
#pragma unroll 4
    for (int n = 0; n < kN; n++) s += p[(size_t)n * kN];
    inv[idx] = 1.f / (s + 1e-8f);
}

// ------- out = (A * inv[m]) @ V, heads merged directly into ctx[b,n,dim] ------
__global__ __launch_bounds__(256) void av_kernel(const float* __restrict__ Sa,
                                                 const float* __restrict__ inv,
                                                 const float* __restrict__ qkv,
                                                 float* __restrict__ ctx) {
    int bh = blockIdx.z;
    int b = bh / kH, h = bh % kH;
    int n0 = blockIdx.y * 64;
    const float* Abase = Sa + (size_t)bh * kN * kN;
    const float* vbase = qkv + (size_t)b * kN * kQD + 2 * kD + h * kHD;
    const float* invb = inv + bh * kN;
    __shared__ __align__(16) float As[16][72];
    __shared__ __align__(16) float Vs[16][72];
    int tid = threadIdx.x;
    int tx = tid & 15, ty = tid >> 4;
    int ar = tid >> 2, ac = (tid & 3) * 4;
    int bk = tid >> 4, bc = (tid & 15) * 4;
    float acc[4][4] = {};
    for (int k0 = 0; k0 < kN; k0 += 16) {
        float4 av = *(const float4*)(Abase + (size_t)(n0 + ar) * kN + k0 + ac);
        float iv = invb[k0 + bk];
        float4 vv = *(const float4*)(vbase + (size_t)(k0 + bk) * kQD + bc);
        As[ac + 0][ar] = av.x; As[ac + 1][ar] = av.y;
        As[ac + 2][ar] = av.z; As[ac + 3][ar] = av.w;
        *(float4*)&Vs[bk][bc] = make_float4(vv.x * iv, vv.y * iv, vv.z * iv, vv.w * iv);
        __syncthreads();
#pragma unroll
        for (int kk = 0; kk < 16; kk++) {
            float4 a = *(const float4*)&As[kk][ty * 4];
            float4 b2 = *(const float4*)&Vs[kk][tx * 4];
            acc[0][0] += a.x * b2.x; acc[0][1] += a.x * b2.y; acc[0][2] += a.x * b2.z; acc[0][3] += a.x * b2.w;
            acc[1][0] += a.y * b2.x; acc[1][1] += a.y * b2.y; acc[1][2] += a.y * b2.z; acc[1][3] += a.y * b2.w;
            acc[2][0] += a.z * b2.x; acc[2][1] += a.z * b2.y; acc[2][2] += a.z * b2.z; acc[2][3] += a.z * b2.w;
            acc[3][0] += a.w * b2.x; acc[3][1] += a.w * b2.y; acc[3][2] += a.w * b2.z; acc[3][3] += a.w * b2.w;
        }
        __syncthreads();
    }
#pragma unroll
    for (int i = 0; i < 4; i++) {
        int n = n0 + ty * 4 + i;
        size_t base = (size_t)(b * kN + n) * kD + h * kHD + tx * 4;
        *(float4*)&ctx[base] = make_float4(acc[i][0], acc[i][1], acc[i][2], acc[i][3]);
    }
}

// ---------------- launch ----------------
extern "C" void kernel_launch(void* const* d_in, const int* in_sizes, int n_in,
                              void* d_out, int out_size) {
    const float* x      = (const float*)d_in[0];
    const float* ln1_w  = (const float*)d_in[1];
    const float* ln1_b  = (const float*)d_in[2];
    const float* qkv_w  = (const float*)d_in[3];
    const float* qkv_b  = (const float*)d_in[4];
    const float* proj_w = (const float*)d_in[5];
    const float* proj_b = (const float*)d_in[6];
    const float* gp_w   = (const float*)d_in[7];
    const float* alpha  = (const float*)d_in[8];
    const float* ln2_w  = (const float*)d_in[9];
    const float* ln2_b  = (const float*)d_in[10];
    const float* ff1_w  = (const float*)d_in[11];
    const float* ff1_b  = (const float*)d_in[12];
    const float* ff2_w  = (const float*)d_in[13];
    const float* ff2_b  = (const float*)d_in[14];
    float* out = (float*)d_out;

    float *xn, *qkv, *S, *G, *gw, *inv, *ctx, *y, *yn, *hdn;
    cudaGetSymbolAddress((void**)&xn,  g_xn);
    cudaGetSymbolAddress((void**)&qkv, g_qkv);
    cudaGetSymbolAddress((void**)&S,   g_S);
    cudaGetSymbolAddress((void**)&G,   g_G);
    cudaGetSymbolAddress((void**)&gw,  g_gw);
    cudaGetSymbolAddress((void**)&inv, g_inv);
    cudaGetSymbolAddress((void**)&ctx, g_ctx);
    cudaGetSymbolAddress((void**)&y,   g_y);
    cudaGetSymbolAddress((void**)&yn,  g_yn);
    cudaGetSymbolAddress((void**)&hdn, g_hdn);

    // attention branch
    ln_kernel<<<kT, 256>>>(x, ln1_w, ln1_b, xn);
    sgemm128_kernel<<<dim3(kQD / 128, kT / 128), 256>>>(xn, qkv_w, qkv_b, nullptr,
                                                        qkv, kT, kQD, kD, 0);
    score_kernel<<<dim3(16, 16, kBH), 256>>>(qkv, S);
    gw_kernel<<<dim3(kN / 64, kBH), 256>>>(qkv, gp_w, gw);
    gmat_kernel<<<dim3(16, 16, kBH), 256>>>(gw, G);
    rowmix_kernel<<<kBH * kN, 256>>>(alpha, S, G);
    colsum_kernel<<<kBH * kN / 256, 256>>>(S, inv);
    av_kernel<<<dim3(1, 16, kBH), 256>>>(S, inv, qkv, ctx);
    sgemm128_kernel<<<dim3(kD / 128, kT / 128), 256>>>(ctx, proj_w, proj_b, x, y,
                                                       kT, kD, kD, 0);
    // FFN branch
    ln_kernel<<<kT, 256>>>(y, ln2_w, ln2_b, yn);
    sgemm128_kernel<<<dim3(kMLP / 128, kT / 128), 256>>>(yn, ff1_w, ff1_b, nullptr,
                                                         hdn, kT, kMLP, kD, 1);
    sgemm128_kernel<<<dim3(kD / 128, kT / 128), 256>>>(hdn, ff2_w, ff2_b, y, out,
                                                       kT, kD, kMLP, 0);
}

// round 4
// speedup vs baseline: 2.6077x; 2.5725x over previous
#include <cuda_runtime.h>
#include <math.h>
#include <stdint.h>

// ---------------- problem constants ----------------
namespace {
constexpr int kB  = 4;
constexpr int kN  = 1024;
constexpr int kD  = 768;
constexpr int kH  = 12;
constexpr int kHD = 64;
constexpr int kGP = 49;
constexpr int kMLP = 3072;
constexpr int kT  = kB * kN;     // 4096 tokens
constexpr int kBH = kB * kH;     // 48 batched heads
constexpr int kQD = 3 * kD;      // 2304
}

// ---------------- scratch (device globals: no allocation allowed) ----------------
__device__ float g_xn [kT * kD];
__device__ float g_qkv[kT * kQD];
__device__ float g_S  [(size_t)kBH * kN * kN];   // scores, later the mixed attn A
__device__ float g_G  [(size_t)kBH * kN * kN];   // gw @ gw^T
__device__ float g_gw [kBH * kN * 64];           // softmaxed group weights, padded 49->64
__device__ float g_inv[kBH * kN];                // 1/(colsum+eps)
__device__ float g_ctx[kT * kD];                 // merged-head attention output
__device__ float g_y  [kT * kD];                 // after proj residual
__device__ float g_yn [kT * kD];
__device__ float g_hdn[kT * kMLP];

__device__ __forceinline__ float gelu_exact(float x) {
    return 0.5f * x * (1.0f + erff(x * 0.70710678118654752440f));
}

__device__ __forceinline__ uint32_t f2tf32(float x) {
    uint32_t r;
    asm("cvt.rna.tf32.f32 %0, %1;" : "=r"(r) : "f"(x));
    return r;
}

// D += A(m16k8,row) * B(k8n8,col)   tf32
__device__ __forceinline__ void mma8(float* c, const uint32_t* a, const uint32_t* b) {
    asm volatile("mma.sync.aligned.m16n8k8.row.col.f32.tf32.tf32.f32 "
                 "{%0,%1,%2,%3}, {%4,%5,%6,%7}, {%8,%9}, {%0,%1,%2,%3};"
                 : "+f"(c[0]), "+f"(c[1]), "+f"(c[2]), "+f"(c[3])
                 : "r"(a[0]), "r"(a[1]), "r"(a[2]), "r"(a[3]),
                   "r"(b[0]), "r"(b[1]));
}

// ---------------- LayerNorm: one block (256 thr) per row of 768 ----------------
__global__ __launch_bounds__(256) void ln_kernel(const float* __restrict__ x,
                                                 const float* __restrict__ w,
                                                 const float* __restrict__ b,
                                                 float* __restrict__ out) {
    __shared__ float sh1[8], sh2[8];
    int row = blockIdx.x;
    int t = threadIdx.x;
    const float* xr = x + (size_t)row * kD;
    float v[3];
    float s = 0.f, s2 = 0.f;
#pragma unroll
    for (int i = 0; i < 3; i++) {
        v[i] = xr[t + i * 256];
        s  += v[i];
        s2 += v[i] * v[i];
    }
#pragma unroll
    for (int o = 16; o; o >>= 1) {
        s  += __shfl_xor_sync(0xffffffffu, s, o);
        s2 += __shfl_xor_sync(0xffffffffu, s2, o);
    }
    if ((t & 31) == 0) { sh1[t >> 5] = s; sh2[t >> 5] = s2; }
    __syncthreads();
    s = sh1[t & 7]; s2 = sh2[t & 7];
#pragma unroll
    for (int o = 4; o; o >>= 1) {
        s  += __shfl_xor_sync(0xffffffffu, s, o);
        s2 += __shfl_xor_sync(0xffffffffu, s2, o);
    }
    float mu   = s * (1.0f / kD);
    float var  = fmaxf(s2 * (1.0f / kD) - mu * mu, 0.f);
    float rstd = rsqrtf(var + 1e-5f);
    float* orow = out + (size_t)row * kD;
#pragma unroll
    for (int i = 0; i < 3; i++) {
        int c = t + i * 256;
        orow[c] = (v[i] - mu) * rstd * w[c] + b[c];
    }
}

// ------- TF32 dense GEMM (NN): C[M,N] = A[M,K] @ B[K,N] + bias (+gelu)(+res) --
// 128x128 block, 8 warps (4m x 2n), each warp m32 x n64, K-step 16.
__global__ __launch_bounds__(256) void gemm_nn_tf32(
        const float* __restrict__ A, const float* __restrict__ B,
        const float* __restrict__ bias, const float* __restrict__ res,
        float* __restrict__ C, int M, int N, int K, int act) {
    __shared__ uint32_t As[128][20];   // [m][k], pad->conflict-free frags
    __shared__ uint32_t Bs[16][136];   // [k][n], pad 8 -> conflict-free frags
    int tid = threadIdx.x, lane = tid & 31, warp = tid >> 5;
    int g = lane >> 2, tg = lane & 3;
    int wm = (warp >> 1) * 32, wn = (warp & 1) * 64;
    int row0 = blockIdx.y * 128, col0 = blockIdx.x * 128;
    float acc[2][8][4] = {};
    for (int k0 = 0; k0 < K; k0 += 16) {
#pragma unroll
        for (int i = 0; i < 2; i++) {
            int idx = tid + i * 256;
            int r = idx >> 2, c4 = (idx & 3) * 4;
            float4 v = *(const float4*)(A + (size_t)(row0 + r) * K + k0 + c4);
            As[r][c4 + 0] = f2tf32(v.x); As[r][c4 + 1] = f2tf32(v.y);
            As[r][c4 + 2] = f2tf32(v.z); As[r][c4 + 3] = f2tf32(v.w);
        }
#pragma unroll
        for (int i = 0; i < 2; i++) {
            int idx = tid + i * 256;
            int kr = idx >> 5, nc = (idx & 31) * 4;
            float4 v = *(const float4*)(B + (size_t)(k0 + kr) * N + col0 + nc);
            Bs[kr][nc + 0] = f2tf32(v.x); Bs[kr][nc + 1] = f2tf32(v.y);
            Bs[kr][nc + 2] = f2tf32(v.z); Bs[kr][nc + 3] = f2tf32(v.w);
        }
        __syncthreads();
#pragma unroll
        for (int k8 = 0; k8 < 16; k8 += 8) {
            uint32_t af[2][4], bf[8][2];
#pragma unroll
            for (int mi = 0; mi < 2; mi++) {
                int r = wm + mi * 16 + g;
                af[mi][0] = As[r][k8 + tg];
                af[mi][1] = As[r + 8][k8 + tg];
                af[mi][2] = As[r][k8 + tg + 4];
                af[mi][3] = As[r + 8][k8 + tg + 4];
            }
#pragma unroll
            for (int nj = 0; nj < 8; nj++) {
                int n = wn + nj * 8 + g;
                bf[nj][0] = Bs[k8 + tg][n];
                bf[nj][1] = Bs[k8 + tg + 4][n];
            }
#pragma unroll
            for (int mi = 0; mi < 2; mi++)
#pragma unroll
                for (int nj = 0; nj < 8; nj++)
                    mma8(acc[mi][nj], af[mi], bf[nj]);
        }
        __syncthreads();
    }
#pragma unroll
    for (int mi = 0; mi < 2; mi++) {
#pragma unroll
        for (int nj = 0; nj < 8; nj++) {
            int r0 = row0 + wm + mi * 16 + g;
            int c = col0 + wn + nj * 8 + tg * 2;
            float b0 = bias[c], b1 = bias[c + 1];
            float o00 = acc[mi][nj][0] + b0, o01 = acc[mi][nj][1] + b1;
            float o10 = acc[mi][nj][2] + b0, o11 = acc[mi][nj][3] + b1;
            if (act) {
                o00 = gelu_exact(o00); o01 = gelu_exact(o01);
                o10 = gelu_exact(o10); o11 = gelu_exact(o11);
            }
            if (res) {
                o00 += res[(size_t)r0 * N + c];       o01 += res[(size_t)r0 * N + c + 1];
                o10 += res[(size_t)(r0 + 8) * N + c]; o11 += res[(size_t)(r0 + 8) * N + c + 1];
            }
            *(float2*)&C[(size_t)r0 * N + c]       = make_float2(o00, o01);
            *(float2*)&C[(size_t)(r0 + 8) * N + c] = make_float2(o10, o11);
        }
    }
}

// ---------------- scores S = scale * Q @ K^T (NT), tf32, batched over BH ------
__global__ __launch_bounds__(256) void score_tf32(const float* __restrict__ qkv,
                                                  float* __restrict__ S) {
    __shared__ uint32_t As[128][20];
    __shared__ uint32_t Bs[128][20];
    int bh = blockIdx.z, b = bh / kH, h = bh % kH;
    const float* qb = qkv + (size_t)b * kN * kQD + h * kHD;
    const float* kb = qb + kD;
    int tid = threadIdx.x, lane = tid & 31, warp = tid >> 5;
    int g = lane >> 2, tg = lane & 3;
    int wm = (warp >> 1) * 32, wn = (warp & 1) * 64;
    int n0 = blockIdx.y * 128, m0 = blockIdx.x * 128;
    float acc[2][8][4] = {};
    for (int k0 = 0; k0 < kHD; k0 += 16) {
#pragma unroll
        for (int i = 0; i < 2; i++) {
            int idx = tid + i * 256;
            int r = idx >> 2, c4 = (idx & 3) * 4;
            float4 qv = *(const float4*)(qb + (size_t)(n0 + r) * kQD + k0 + c4);
            float4 kv = *(const float4*)(kb + (size_t)(m0 + r) * kQD + k0 + c4);
            As[r][c4 + 0] = f2tf32(qv.x); As[r][c4 + 1] = f2tf32(qv.y);
            As[r][c4 + 2] = f2tf32(qv.z); As[r][c4 + 3] = f2tf32(qv.w);
            Bs[r][c4 + 0] = f2tf32(kv.x); Bs[r][c4 + 1] = f2tf32(kv.y);
            Bs[r][c4 + 2] = f2tf32(kv.z); Bs[r][c4 + 3] = f2tf32(kv.w);
        }
        __syncthreads();
#pragma unroll
        for (int k8 = 0; k8 < 16; k8 += 8) {
            uint32_t af[2][4], bf[8][2];
#pragma unroll
            for (int mi = 0; mi < 2; mi++) {
                int r = wm + mi * 16 + g;
                af[mi][0] = As[r][k8 + tg];
                af[mi][1] = As[r + 8][k8 + tg];
                af[mi][2] = As[r][k8 + tg + 4];
                af[mi][3] = As[r + 8][k8 + tg + 4];
            }
#pragma unroll
            for (int nj = 0; nj < 8; nj++) {
                int n = wn + nj * 8 + g;
                bf[nj][0] = Bs[n][k8 + tg];
                bf[nj][1] = Bs[n][k8 + tg + 4];
            }
#pragma unroll
            for (int mi = 0; mi < 2; mi++)
#pragma unroll
                for (int nj = 0; nj < 8; nj++)
                    mma8(acc[mi][nj], af[mi], bf[nj]);
        }
        __syncthreads();
    }
    float* Sb = S + (size_t)bh * kN * kN;
#pragma unroll
    for (int mi = 0; mi < 2; mi++) {
#pragma unroll
        for (int nj = 0; nj < 8; nj++) {
            int r0 = n0 + wm + mi * 16 + g;
            int c = m0 + wn + nj * 8 + tg * 2;
            *(float2*)&Sb[(size_t)r0 * kN + c] =
                make_float2(acc[mi][nj][0] * 0.125f, acc[mi][nj][1] * 0.125f);
            *(float2*)&Sb[(size_t)(r0 + 8) * kN + c] =
                make_float2(acc[mi][nj][2] * 0.125f, acc[mi][nj][3] * 0.125f);
        }
    }
}

// ---------------- G = gw @ gw^T (NT), tf32, K=64 padded ----------------
__global__ __launch_bounds__(256) void gmat_tf32(const float* __restrict__ gw,
                                                 float* __restrict__ G) {
    __shared__ uint32_t As[128][20];
    __shared__ uint32_t Bs[128][20];
    int bh = blockIdx.z;
    const float* gb = gw + (size_t)bh * kN * 64;
    int tid = threadIdx.x, lane = tid & 31, warp = tid >> 5;
    int g = lane >> 2, tg = lane & 3;
    int wm = (warp >> 1) * 32, wn = (warp & 1) * 64;
    int n0 = blockIdx.y * 128, m0 = blockIdx.x * 128;
    float acc[2][8][4] = {};
    for (int k0 = 0; k0 < 64; k0 += 16) {
#pragma unroll
        for (int i = 0; i < 2; i++) {
            int idx = tid + i * 256;
            int r = idx >> 2, c4 = (idx & 3) * 4;
            float4 av = *(const float4*)(gb + (size_t)(n0 + r) * 64 + k0 + c4);
            float4 bv = *(const float4*)(gb + (size_t)(m0 + r) * 64 + k0 + c4);
            As[r][c4 + 0] = f2tf32(av.x); As[r][c4 + 1] = f2tf32(av.y);
            As[r][c4 + 2] = f2tf32(av.z); As[r][c4 + 3] = f2tf32(av.w);
            Bs[r][c4 + 0] = f2tf32(bv.x); Bs[r][c4 + 1] = f2tf32(bv.y);
            Bs[r][c4 + 2] = f2tf32(bv.z); Bs[r][c4 + 3] = f2tf32(bv.w);
        }
        __syncthreads();
#pragma unroll
        for (int k8 = 0; k8 < 16; k8 += 8) {
            uint32_t af[2][4], bf[8][2];
#pragma unroll
            for (int mi = 0; mi < 2; mi++) {
                int r = wm + mi * 16 + g;
                af[mi][0] = As[r][k8 + tg];
                af[mi][1] = As[r + 8][k8 + tg];
                af[mi][2] = As[r][k8 + tg + 4];
                af[mi][3] = As[r + 8][k8 + tg + 4];
            }
#pragma unroll
            for (int nj = 0; nj < 8; nj++) {
                int n = wn + nj * 8 + g;
                bf[nj][0] = Bs[n][k8 + tg];
                bf[nj][1] = Bs[n][k8 + tg + 4];
            }
#pragma unroll
            for (int mi = 0; mi < 2; mi++)
#pragma unroll
                for (int nj = 0; nj < 8; nj++)
                    mma8(acc[mi][nj], af[mi], bf[nj]);
        }
        __syncthreads();
    }
    float* Gb = G + (size_t)bh * kN * kN;
#pragma unroll
    for (int mi = 0; mi < 2; mi++) {
#pragma unroll
        for (int nj = 0; nj < 8; nj++) {
            int r0 = n0 + wm + mi * 16 + g;
            int c = m0 + wn + nj * 8 + tg * 2;
            *(float2*)&Gb[(size_t)r0 * kN + c] =
                make_float2(acc[mi][nj][0], acc[mi][nj][1]);
            *(float2*)&Gb[(size_t)(r0 + 8) * kN + c] =
                make_float2(acc[mi][nj][2], acc[mi][nj][3]);
        }
    }
}

// ------- out = (A * inv[k]) @ V  (NN), tf32; heads merged into ctx ------------
// 128x64 block, 8 warps (4m x 2n), each warp m32 x n32.
__global__ __launch_bounds__(256) void av_tf32(const float* __restrict__ Sa,
                                               const float* __restrict__ inv,
                                               const float* __restrict__ qkv,
                                               float* __restrict__ ctx) {
    __shared__ uint32_t As[128][20];
    __shared__ uint32_t Bs[16][72];
    int bh = blockIdx.z, b = bh / kH, h = bh % kH;
    const float* Ab = Sa + (size_t)bh * kN * kN;
    const float* vb = qkv + (size_t)b * kN * kQD + 2 * kD + h * kHD;
    const float* invb = inv + bh * kN;
    int tid = threadIdx.x, lane = tid & 31, warp = tid >> 5;
    int g = lane >> 2, tg = lane & 3;
    int wm = (warp >> 1) * 32, wn = (warp & 1) * 32;
    int row0 = blockIdx.y * 128;
    float acc[2][4][4] = {};
    for (int k0 = 0; k0 < kN; k0 += 16) {
#pragma unroll
        for (int i = 0; i < 2; i++) {
            int idx = tid + i * 256;
            int r = idx >> 2, c4 = (idx & 3) * 4;
            float4 v = *(const float4*)(Ab + (size_t)(row0 + r) * kN + k0 + c4);
            As[r][c4 + 0] = f2tf32(v.x); As[r][c4 + 1] = f2tf32(v.y);
            As[r][c4 + 2] = f2tf32(v.z); As[r][c4 + 3] = f2tf32(v.w);
        }
        {
            int kr = tid >> 4, nc = (tid & 15) * 4;
            float iv = invb[k0 + kr];
            float4 v = *(const float4*)(vb + (size_t)(k0 + kr) * kQD + nc);
            Bs[kr][nc + 0] = f2tf32(v.x * iv); Bs[kr][nc + 1] = f2tf32(v.y * iv);
            Bs[kr][nc + 2] = f2tf32(v.z * iv); Bs[kr][nc + 3] = f2tf32(v.w * iv);
        }
        __syncthreads();
#pragma unroll
        for (int k8 = 0; k8 < 16; k8 += 8) {
            uint32_t af[2][4], bf[4][2];
#pragma unroll
            for (int mi = 0; mi < 2; mi++) {
                int r = wm + mi * 16 + g;
                af[mi][0] = As[r][k8 + tg];
                af[mi][1] = As[r + 8][k8 + tg];
                af[mi][2] = As[r][k8 + tg + 4];
                af[mi][3] = As[r + 8][k8 + tg + 4];
            }
#pragma unroll
            for (int nj = 0; nj < 4; nj++) {
                int n = wn + nj * 8 + g;
                bf[nj][0] = Bs[k8 + tg][n];
                bf[nj][1] = Bs[k8 + tg + 4][n];
            }
#pragma unroll
            for (int mi = 0; mi < 2; mi++)
#pragma unroll
                for (int nj = 0; nj < 4; nj++)
                    mma8(acc[mi][nj], af[mi], bf[nj]);
        }
        __syncthreads();
    }
#pragma unroll
    for (int mi = 0; mi < 2; mi++) {
#pragma unroll
        for (int nj = 0; nj < 4; nj++) {
            int tok0 = b * kN + row0 + wm + mi * 16 + g;
            int c = h * kHD + wn + nj * 8 + tg * 2;
            *(float2*)&ctx[(size_t)tok0 * kD + c] =
                make_float2(acc[mi][nj][0], acc[mi][nj][1]);
            *(float2*)&ctx[(size_t)(tok0 + 8) * kD + c] =
                make_float2(acc[mi][nj][2], acc[mi][nj][3]);
        }
    }
}

// ---- group weights: gw = softmax(gelu(V @ gp^T)) padded to 64 ----
__global__ __launch_bounds__(256) void gw_kernel(const float* __restrict__ qkv,
                                                 const float* __restrict__ gp_w,
                                                 float* __restrict__ gw) {
    __shared__ __align__(16) float gps[kGP][68];
    __shared__ __align__(16) float Vs[64][68];
    int bh = blockIdx.y;
    int b = bh / kH, h = bh % kH;
    int n0 = blockIdx.x * 64;
    int tid = threadIdx.x;
    const float* gph = gp_w + (size_t)h * kGP * kHD;
    for (int i = tid; i < kGP * 16; i += 256) {
        int r = i >> 4, c4 = (i & 15) * 4;
        *(float4*)&gps[r][c4] = *(const float4*)(gph + r * kHD + c4);
    }
    const float* vb = qkv + (size_t)(b * kN + n0) * kQD + 2 * kD + h * kHD;
    for (int i = tid; i < 64 * 16; i += 256) {
        int r = i >> 4, c4 = (i & 15) * 4;
        *(float4*)&Vs[r][c4] = *(const float4*)(vb + (size_t)r * kQD + c4);
    }
    __syncthreads();
    int r = tid >> 2;
    int c0 = tid & 3;
    float val[13];
    float mx = -1e30f;
#pragma unroll
    for (int j = 0; j < 13; j++) {
        int c = c0 + 4 * j;
        float acc = 0.f;
        if (c < kGP) {
#pragma unroll
            for (int d = 0; d < kHD; d += 4) {
                float4 vv = *(const float4*)&Vs[r][d];
                float4 gg = *(const float4*)&gps[c][d];
                acc += vv.x * gg.x + vv.y * gg.y + vv.z * gg.z + vv.w * gg.w;
            }
            acc = gelu_exact(acc);
            mx = fmaxf(mx, acc);
        }
        val[j] = acc;
    }
    mx = fmaxf(mx, __shfl_xor_sync(0xffffffffu, mx, 1));
    mx = fmaxf(mx, __shfl_xor_sync(0xffffffffu, mx, 2));
    float sum = 0.f;
#pragma unroll
    for (int j = 0; j < 13; j++) {
        int c = c0 + 4 * j;
        val[j] = (c < kGP) ? __expf(val[j] - mx) : 0.f;
        sum += val[j];
    }
    sum += __shfl_xor_sync(0xffffffffu, sum, 1);
    sum += __shfl_xor_sync(0xffffffffu, sum, 2);
    float is = 1.f / sum;
    float* grow = gw + (size_t)(bh * kN + n0 + r) * 64;
#pragma unroll
    for (int j = 0; j < 16; j++) {
        int c = c0 + 4 * j;
        if (c < 64) grow[c] = (j < 13 && c < kGP) ? val[j] * is : 0.f;
    }
}

// ------- per-row: P = softmax(S*G); A = (1-a)P + a*G  (A overwrites S) -------
__global__ __launch_bounds__(256) void rowmix_kernel(const float* __restrict__ alpha,
                                                     float* __restrict__ S,
                                                     const float* __restrict__ G) {
    __shared__ float sh1[8];
    int gr = blockIdx.x;                 // bh*N + n
    int h = (gr >> 10) % kH;
    size_t off = (size_t)gr * kN;
    int t = threadIdx.x;
    float a = 1.f / (1.f + __expf(-alpha[h]));
    float gv[4], tv[4];
    float mx = -1e30f;
#pragma unroll
    for (int i = 0; i < 4; i++) {
        int m = t + i * 256;
        float sv = S[off + m];
        gv[i] = G[off + m];
        tv[i] = sv * gv[i];
        mx = fmaxf(mx, tv[i]);
    }
    for (int o = 16; o; o >>= 1) mx = fmaxf(mx, __shfl_xor_sync(0xffffffffu, mx, o));
    if ((t & 31) == 0) sh1[t >> 5] = mx;
    __syncthreads();
    mx = sh1[t & 7];
    for (int o = 4; o; o >>= 1) mx = fmaxf(mx, __shfl_xor_sync(0xffffffffu, mx, o));
    __syncthreads();
    float e[4], sum = 0.f;
#pragma unroll
    for (int i = 0; i < 4; i++) { e[i] = __expf(tv[i] - mx); sum += e[i]; }
    for (int o = 16; o; o >>= 1) sum += __shfl_xor_sync(0xffffffffu, sum, o);
    if ((t & 31) == 0) sh1[t >> 5] = sum;
    __syncthreads();
    sum = sh1[t & 7];
    for (int o = 4; o; o >>= 1) sum += __shfl_xor_sync(0xffffffffu, sum, o);
    float isum = 1.f / sum;
#pragma unroll
    for (int i = 0; i < 4; i++) {
        int m = t + i * 256;
        S[off + m] = (1.f - a) * e[i] * isum + a * gv[i];
    }
}

// ------- column sums over n (axis=2), stores 1/(sum+1e-8) -------
__global__ __launch_bounds__(256) void colsum_kernel(const float* __restrict__ Sa,
                                                     float* __restrict__ inv) {
    int idx = blockIdx.x * 256 + threadIdx.x;   // bh*N + m
    int bh = idx >> 10, m = idx & 1023;
    const float* p = Sa + (size_t)bh * kN * kN + m;
    float s = 0.f;
#pragma unroll 4
    for (int n = 0; n < kN; n++) s += p[(size_t)n * kN];
    inv[idx] = 1.f / (s + 1e-8f);
}

// ---------------- launch ----------------
extern "C" void kernel_launch(void* const* d_in, const int* in_sizes, int n_in,
                              void* d_out, int out_size) {
    const float* x      = (const float*)d_in[0];
    const float* ln1_w  = (const float*)d_in[1];
    const float* ln1_b  = (const float*)d_in[2];
    const float* qkv_w  = (const float*)d_in[3];
    const float* qkv_b  = (const float*)d_in[4];
    const float* proj_w = (const float*)d_in[5];
    const float* proj_b = (const float*)d_in[6];
    const float* gp_w   = (const float*)d_in[7];
    const float* alpha  = (const float*)d_in[8];
    const float* ln2_w  = (const float*)d_in[9];
    const float* ln2_b  = (const float*)d_in[10];
    const float* ff1_w  = (const float*)d_in[11];
    const float* ff1_b  = (const float*)d_in[12];
    const float* ff2_w  = (const float*)d_in[13];
    const float* ff2_b  = (const float*)d_in[14];
    float* out = (float*)d_out;

    float *xn, *qkv, *S, *G, *gw, *inv, *ctx, *y, *yn, *hdn;
    cudaGetSymbolAddress((void**)&xn,  g_xn);
    cudaGetSymbolAddress((void**)&qkv, g_qkv);
    cudaGetSymbolAddress((void**)&S,   g_S);
    cudaGetSymbolAddress((void**)&G,   g_G);
    cudaGetSymbolAddress((void**)&gw,  g_gw);
    cudaGetSymbolAddress((void**)&inv, g_inv);
    cudaGetSymbolAddress((void**)&ctx, g_ctx);
    cudaGetSymbolAddress((void**)&y,   g_y);
    cudaGetSymbolAddress((void**)&yn,  g_yn);
    cudaGetSymbolAddress((void**)&hdn, g_hdn);

    // attention branch
    ln_kernel<<<kT, 256>>>(x, ln1_w, ln1_b, xn);
    gemm_nn_tf32<<<dim3(kQD / 128, kT / 128), 256>>>(xn, qkv_w, qkv_b, nullptr,
                                                     qkv, kT, kQD, kD, 0);
    score_tf32<<<dim3(8, 8, kBH), 256>>>(qkv, S);
    gw_kernel<<<dim3(kN / 64, kBH), 256>>>(qkv, gp_w, gw);
    gmat_tf32<<<dim3(8, 8, kBH), 256>>>(gw, G);
    rowmix_kernel<<<kBH * kN, 256>>>(alpha, S, G);
    colsum_kernel<<<kBH * kN / 256, 256>>>(S, inv);
    av_tf32<<<dim3(1, 8, kBH), 256>>>(S, inv, qkv, ctx);
    gemm_nn_tf32<<<dim3(kD / 128, kT / 128), 256>>>(ctx, proj_w, proj_b, x, y,
                                                    kT, kD, kD, 0);
    // FFN branch
    ln_kernel<<<kT, 256>>>(y, ln2_w, ln2_b, yn);
    gemm_nn_tf32<<<dim3(kMLP / 128, kT / 128), 256>>>(yn, ff1_w, ff1_b, nullptr,
                                                      hdn, kT, kMLP, kD, 1);
    gemm_nn_tf32<<<dim3(kD / 128, kT / 128), 256>>>(hdn, ff2_w, ff2_b, y, out,
                                                    kT, kD, kMLP, 0);
}